// round 4
// baseline (speedup 1.0000x reference)
#include <cuda_runtime.h>
#include <cstdint>

#define F_DIM    48
#define CHUNKS   12            // 48 floats = 12 float4 per node
#define N_NODES  100000
#define N_EDGES  1600000

#define SCAN_TPB     1024
#define SCAN_ELEMS   (N_NODES + 1)                       // 100001
#define SCAN_NBLK    ((SCAN_ELEMS + SCAN_TPB - 1) / SCAN_TPB)   // 98

// ---------------------------------------------------------------------------
// Scratch (__device__ globals — no allocation)
// ---------------------------------------------------------------------------
__device__ float4 g_xw[N_NODES * CHUNKS];     // x * w, 19.2 MB
__device__ int    g_count[N_NODES + 1];       // histogram -> offsets
__device__ int    g_pos[N_NODES];             // running write cursor
__device__ int    g_blocksums[SCAN_NBLK];
__device__ int    g_ecol[N_EDGES];            // row-sorted cols
__device__ float  g_eval[N_EDGES];            // row-sorted vals

// ---------------------------------------------------------------------------
// 1. prologue: xw = x*w ; zero histogram
// ---------------------------------------------------------------------------
__global__ __launch_bounds__(256)
void prologue_kernel(const float4* __restrict__ x4,
                     const float4* __restrict__ w4) {
    int i = blockIdx.x * blockDim.x + threadIdx.x;
    if (i < N_NODES * CHUNKS) {
        int c = i % CHUNKS;
        float4 xv = x4[i];
        float4 wv = __ldg(w4 + c);
        xv.x *= wv.x; xv.y *= wv.y; xv.z *= wv.z; xv.w *= wv.w;
        g_xw[i] = xv;
    }
    if (i <= N_NODES) g_count[i] = 0;
}

// ---------------------------------------------------------------------------
// 2. histogram: count edges per destination row (offset by +1)
// ---------------------------------------------------------------------------
__global__ __launch_bounds__(256)
void hist_kernel(const int* __restrict__ rows, int nE) {
    int e = blockIdx.x * blockDim.x + threadIdx.x;
    if (e < nE) atomicAdd(&g_count[rows[e] + 1], 1);
}

// ---------------------------------------------------------------------------
// 3a. block-local inclusive scan (1024 elems/block)
// ---------------------------------------------------------------------------
__global__ __launch_bounds__(SCAN_TPB)
void scan1_kernel() {
    __shared__ int buf[2][SCAN_TPB];
    int t = threadIdx.x;
    int idx = blockIdx.x * SCAN_TPB + t;
    int v = (idx < SCAN_ELEMS) ? g_count[idx] : 0;
    int src = 0;
    buf[0][t] = v;
    __syncthreads();
    #pragma unroll
    for (int off = 1; off < SCAN_TPB; off <<= 1) {
        int val = buf[src][t];
        if (t >= off) val += buf[src][t - off];
        buf[src ^ 1][t] = val;
        src ^= 1;
        __syncthreads();
    }
    if (idx < SCAN_ELEMS) g_count[idx] = buf[src][t];
    if (t == SCAN_TPB - 1) g_blocksums[blockIdx.x] = buf[src][t];
}

// 3b. scan the block sums (single block)
__global__ __launch_bounds__(128)
void scan2_kernel() {
    __shared__ int buf[2][128];
    int t = threadIdx.x;
    int v = (t < SCAN_NBLK) ? g_blocksums[t] : 0;
    int src = 0;
    buf[0][t] = v;
    __syncthreads();
    #pragma unroll
    for (int off = 1; off < 128; off <<= 1) {
        int val = buf[src][t];
        if (t >= off) val += buf[src][t - off];
        buf[src ^ 1][t] = val;
        src ^= 1;
        __syncthreads();
    }
    if (t < SCAN_NBLK) g_blocksums[t] = buf[src][t];
}

// 3c. add block offsets; init write cursors
__global__ __launch_bounds__(SCAN_TPB)
void scan3_kernel() {
    int t = threadIdx.x;
    int idx = blockIdx.x * SCAN_TPB + t;
    if (idx >= SCAN_ELEMS) return;
    int v = g_count[idx];
    if (blockIdx.x > 0) {
        v += g_blocksums[blockIdx.x - 1];
        g_count[idx] = v;
    }
    if (idx < N_NODES) g_pos[idx] = v;   // start offset of node idx
}

// ---------------------------------------------------------------------------
// 4. reorder edges into row-sorted order
// ---------------------------------------------------------------------------
__global__ __launch_bounds__(256)
void reorder_kernel(const int*   __restrict__ rows,
                    const int*   __restrict__ cols,
                    const float* __restrict__ vals, int nE) {
    int e = blockIdx.x * blockDim.x + threadIdx.x;
    if (e >= nE) return;
    int p = atomicAdd(&g_pos[rows[e]], 1);
    g_ecol[p] = cols[e];
    g_eval[p] = vals[e];
}

// ---------------------------------------------------------------------------
// 5. gather: 12 lanes per node, register accumulation, single write.
//    No atomics. xw gather is 192B-contiguous per edge; meta is broadcast.
// ---------------------------------------------------------------------------
__global__ __launch_bounds__(256)
void gather_kernel(float4* __restrict__ out4) {
    int gid = blockIdx.x * blockDim.x + threadIdx.x;
    int node = gid / CHUNKS;
    int c = gid - node * CHUNKS;
    if (node >= N_NODES) return;

    const int start = __ldg(&g_count[node]);
    const int end   = __ldg(&g_count[node + 1]);

    float4 acc = make_float4(0.f, 0.f, 0.f, 0.f);
    int e = start;
    for (; e + 1 < end; e += 2) {
        int   col0 = __ldg(g_ecol + e);
        int   col1 = __ldg(g_ecol + e + 1);
        float v0   = __ldg(g_eval + e);
        float v1   = __ldg(g_eval + e + 1);
        float4 a = g_xw[(size_t)col0 * CHUNKS + c];
        float4 b = g_xw[(size_t)col1 * CHUNKS + c];
        acc.x += v0 * a.x + v1 * b.x;
        acc.y += v0 * a.y + v1 * b.y;
        acc.z += v0 * a.z + v1 * b.z;
        acc.w += v0 * a.w + v1 * b.w;
    }
    if (e < end) {
        int   col0 = __ldg(g_ecol + e);
        float v0   = __ldg(g_eval + e);
        float4 a = g_xw[(size_t)col0 * CHUNKS + c];
        acc.x += v0 * a.x;
        acc.y += v0 * a.y;
        acc.z += v0 * a.z;
        acc.w += v0 * a.w;
    }
    out4[(size_t)node * CHUNKS + c] = acc;
}

// ---------------------------------------------------------------------------
// Launch
// Inputs: 0 x[1,100000,48] f32 | 1 w[1,48] f32 | 2 rows[1.6M] i32
//         3 cols[1.6M] i32     | 4 vals[1.6M] f32
// Output: f32 [100000, 48]
// ---------------------------------------------------------------------------
extern "C" void kernel_launch(void* const* d_in, const int* in_sizes, int n_in,
                              void* d_out, int out_size) {
    const float* x    = (const float*)d_in[0];
    const float* w    = (const float*)d_in[1];
    const int*   rows = (const int*)  d_in[2];
    const int*   cols = (const int*)  d_in[3];
    const float* vals = (const float*)d_in[4];
    float*       out  = (float*)d_out;

    const int nE = in_sizes[2];

    // 1. prologue
    {
        int n = N_NODES * CHUNKS;
        prologue_kernel<<<(n + 255) / 256, 256>>>((const float4*)x,
                                                  (const float4*)w);
    }
    // 2. histogram
    hist_kernel<<<(nE + 255) / 256, 256>>>(rows, nE);
    // 3. scan
    scan1_kernel<<<SCAN_NBLK, SCAN_TPB>>>();
    scan2_kernel<<<1, 128>>>();
    scan3_kernel<<<SCAN_NBLK, SCAN_TPB>>>();
    // 4. reorder
    reorder_kernel<<<(nE + 255) / 256, 256>>>(rows, cols, vals, nE);
    // 5. gather
    {
        int n = N_NODES * CHUNKS;
        gather_kernel<<<(n + 255) / 256, 256>>>((float4*)out);
    }
}

// round 5
// speedup vs baseline: 1.1121x; 1.1121x over previous
#include <cuda_runtime.h>
#include <cstdint>

#define F_DIM    48
#define CHUNKS   12            // 48 floats = 12 float4 per node
#define N_NODES  100000
#define N_EDGES  1600000

#define SCAN_TPB   1024
#define SCAN_ELEMS (N_NODES + 1)                                // 100001
#define SCAN_NBLK  ((SCAN_ELEMS + SCAN_TPB - 1) / SCAN_TPB)     // 98

// ---------------------------------------------------------------------------
// Scratch (__device__ globals — no allocation)
// ---------------------------------------------------------------------------
__device__ int  g_count[N_NODES + 1];     // histogram -> CSR offsets
__device__ int  g_pos[N_NODES];           // running write cursors
__device__ int  g_blocksums[SCAN_NBLK];
__device__ int2 g_edge[N_EDGES];          // row-sorted {col, val-bits}

// ---------------------------------------------------------------------------
// 1. histogram (g_count zeroed beforehand by cudaMemsetAsync)
// ---------------------------------------------------------------------------
__global__ __launch_bounds__(256)
void hist_kernel(const int* __restrict__ rows, int nE) {
    int e = blockIdx.x * blockDim.x + threadIdx.x;
    if (e < nE) atomicAdd(&g_count[rows[e] + 1], 1);
}

// ---------------------------------------------------------------------------
// 2a. block-local inclusive scan (1024 elems/block) + block sums
// ---------------------------------------------------------------------------
__global__ __launch_bounds__(SCAN_TPB)
void scan1_kernel() {
    __shared__ int buf[2][SCAN_TPB];
    int t = threadIdx.x;
    int idx = blockIdx.x * SCAN_TPB + t;
    int v = (idx < SCAN_ELEMS) ? g_count[idx] : 0;
    int src = 0;
    buf[0][t] = v;
    __syncthreads();
    #pragma unroll
    for (int off = 1; off < SCAN_TPB; off <<= 1) {
        int val = buf[src][t];
        if (t >= off) val += buf[src][t - off];
        buf[src ^ 1][t] = val;
        src ^= 1;
        __syncthreads();
    }
    if (idx < SCAN_ELEMS) g_count[idx] = buf[src][t];
    if (t == SCAN_TPB - 1) g_blocksums[blockIdx.x] = buf[src][t];
}

// ---------------------------------------------------------------------------
// 2b. fixup: add prefix of block sums (inlined uniform loop over <=98 values);
//     init write cursors g_pos.
// ---------------------------------------------------------------------------
__global__ __launch_bounds__(SCAN_TPB)
void scan2_kernel() {
    int t = threadIdx.x;
    int idx = blockIdx.x * SCAN_TPB + t;
    if (idx >= SCAN_ELEMS) return;

    int base = 0;
    // Uniform across the block: all threads read the same small sequence
    // (broadcast LDG, L1-resident). blockIdx.x <= 97.
    for (int b = 0; b < blockIdx.x; b++) base += __ldg(&g_blocksums[b]);

    int v = g_count[idx] + base;
    if (blockIdx.x > 0) g_count[idx] = v;
    if (idx < N_NODES) g_pos[idx] = v;
}

// ---------------------------------------------------------------------------
// 3. reorder: permute edges into row-sorted order, one packed 8B store each
// ---------------------------------------------------------------------------
__global__ __launch_bounds__(256)
void reorder_kernel(const int*   __restrict__ rows,
                    const int*   __restrict__ cols,
                    const float* __restrict__ vals, int nE) {
    int e = blockIdx.x * blockDim.x + threadIdx.x;
    if (e >= nE) return;
    int p = atomicAdd(&g_pos[rows[e]], 1);
    g_edge[p] = make_int2(cols[e], __float_as_int(vals[e]));
}

// ---------------------------------------------------------------------------
// 4. gather: 12 lanes per node, register accumulation, w applied at the end,
//    single output write. No atomics. 4-deep unroll for MLP.
// ---------------------------------------------------------------------------
__global__ __launch_bounds__(256)
void gather_kernel(const float*  __restrict__ x,
                   const float4* __restrict__ w4,
                   float4*       __restrict__ out4) {
    int gid = blockIdx.x * blockDim.x + threadIdx.x;
    int node = gid / CHUNKS;
    int c = gid - node * CHUNKS;
    if (node >= N_NODES) return;

    const int start = __ldg(&g_count[node]);
    const int end   = __ldg(&g_count[node + 1]);

    float4 acc = make_float4(0.f, 0.f, 0.f, 0.f);
    int e = start;
    for (; e + 3 < end; e += 4) {
        int2 m0 = __ldg(g_edge + e + 0);
        int2 m1 = __ldg(g_edge + e + 1);
        int2 m2 = __ldg(g_edge + e + 2);
        int2 m3 = __ldg(g_edge + e + 3);
        float4 a0 = *reinterpret_cast<const float4*>(x + (size_t)m0.x * F_DIM + c * 4);
        float4 a1 = *reinterpret_cast<const float4*>(x + (size_t)m1.x * F_DIM + c * 4);
        float4 a2 = *reinterpret_cast<const float4*>(x + (size_t)m2.x * F_DIM + c * 4);
        float4 a3 = *reinterpret_cast<const float4*>(x + (size_t)m3.x * F_DIM + c * 4);
        float v0 = __int_as_float(m0.y), v1 = __int_as_float(m1.y);
        float v2 = __int_as_float(m2.y), v3 = __int_as_float(m3.y);
        acc.x += v0 * a0.x + v1 * a1.x + v2 * a2.x + v3 * a3.x;
        acc.y += v0 * a0.y + v1 * a1.y + v2 * a2.y + v3 * a3.y;
        acc.z += v0 * a0.z + v1 * a1.z + v2 * a2.z + v3 * a3.z;
        acc.w += v0 * a0.w + v1 * a1.w + v2 * a2.w + v3 * a3.w;
    }
    for (; e < end; e++) {
        int2 m = __ldg(g_edge + e);
        float4 a = *reinterpret_cast<const float4*>(x + (size_t)m.x * F_DIM + c * 4);
        float v = __int_as_float(m.y);
        acc.x += v * a.x;
        acc.y += v * a.y;
        acc.z += v * a.z;
        acc.w += v * a.w;
    }

    // apply w once, per output element (L1-resident 192B)
    float4 wv = __ldg(w4 + c);
    acc.x *= wv.x; acc.y *= wv.y; acc.z *= wv.z; acc.w *= wv.w;

    out4[(size_t)node * CHUNKS + c] = acc;
}

// ---------------------------------------------------------------------------
// Launch
// Inputs: 0 x[1,100000,48] f32 | 1 w[1,48] f32 | 2 rows[1.6M] i32
//         3 cols[1.6M] i32     | 4 vals[1.6M] f32
// Output: f32 [100000, 48]
// ---------------------------------------------------------------------------
extern "C" void kernel_launch(void* const* d_in, const int* in_sizes, int n_in,
                              void* d_out, int out_size) {
    const float* x    = (const float*)d_in[0];
    const float* w    = (const float*)d_in[1];
    const int*   rows = (const int*)  d_in[2];
    const int*   cols = (const int*)  d_in[3];
    const float* vals = (const float*)d_in[4];
    float*       out  = (float*)d_out;

    const int nE = in_sizes[2];

    // 0. zero histogram (capturable async memset; no allocation)
    void* count_ptr = nullptr;
    cudaGetSymbolAddress(&count_ptr, g_count);
    cudaMemsetAsync(count_ptr, 0, (N_NODES + 1) * sizeof(int), 0);

    // 1. histogram
    hist_kernel<<<(nE + 255) / 256, 256>>>(rows, nE);
    // 2. scan (2 kernels)
    scan1_kernel<<<SCAN_NBLK, SCAN_TPB>>>();
    scan2_kernel<<<SCAN_NBLK, SCAN_TPB>>>();
    // 3. reorder
    reorder_kernel<<<(nE + 255) / 256, 256>>>(rows, cols, vals, nE);
    // 4. gather
    {
        int n = N_NODES * CHUNKS;
        gather_kernel<<<(n + 255) / 256, 256>>>(x, (const float4*)w,
                                                (float4*)out);
    }
}

// round 6
// speedup vs baseline: 1.1236x; 1.0103x over previous
#include <cuda_runtime.h>
#include <cstdint>

#define F_DIM    48
#define CHUNKS   12            // 48 floats = 12 float4 per node
#define N_NODES  100000
#define N_EDGES  1600000

#define SCAN_TPB   1024
#define SCAN_ELEMS (N_NODES + 1)                                // 100001
#define SCAN_NBLK  ((SCAN_ELEMS + SCAN_TPB - 1) / SCAN_TPB)     // 98

// ---------------------------------------------------------------------------
// Scratch (__device__ globals — no allocation)
// ---------------------------------------------------------------------------
__device__ int  g_count[N_NODES + 1];     // histogram -> CSR offsets
__device__ int  g_rank[N_EDGES];          // rank of edge within its row
__device__ int  g_blocksums[SCAN_NBLK];
__device__ int2 g_edge[N_EDGES];          // row-sorted {col, val-bits}

// ---------------------------------------------------------------------------
// 1. histogram + per-edge rank capture (g_count pre-zeroed by memsetAsync).
//    The atomic return value is stored, never depended on -> latency hidden.
// ---------------------------------------------------------------------------
__global__ __launch_bounds__(256)
void hist_kernel(const int* __restrict__ rows, int nE) {
    int e = blockIdx.x * blockDim.x + threadIdx.x;
    if (e < nE) {
        int r = __ldg(rows + e);
        g_rank[e] = atomicAdd(&g_count[r + 1], 1);
    }
}

// ---------------------------------------------------------------------------
// 2a. block-local inclusive scan (1024 elems/block) + block sums
// ---------------------------------------------------------------------------
__global__ __launch_bounds__(SCAN_TPB)
void scan1_kernel() {
    __shared__ int buf[2][SCAN_TPB];
    int t = threadIdx.x;
    int idx = blockIdx.x * SCAN_TPB + t;
    int v = (idx < SCAN_ELEMS) ? g_count[idx] : 0;
    int src = 0;
    buf[0][t] = v;
    __syncthreads();
    #pragma unroll
    for (int off = 1; off < SCAN_TPB; off <<= 1) {
        int val = buf[src][t];
        if (t >= off) val += buf[src][t - off];
        buf[src ^ 1][t] = val;
        src ^= 1;
        __syncthreads();
    }
    if (idx < SCAN_ELEMS) g_count[idx] = buf[src][t];
    if (t == SCAN_TPB - 1) g_blocksums[blockIdx.x] = buf[src][t];
}

// ---------------------------------------------------------------------------
// 2b. fixup: add prefix of block sums (uniform broadcast loop, <=97 iters)
// ---------------------------------------------------------------------------
__global__ __launch_bounds__(SCAN_TPB)
void scan2_kernel() {
    int t = threadIdx.x;
    int idx = blockIdx.x * SCAN_TPB + t;
    if (idx >= SCAN_ELEMS || blockIdx.x == 0) return;

    int base = 0;
    for (int b = 0; b < blockIdx.x; b++) base += __ldg(&g_blocksums[b]);
    g_count[idx] += base;
}

// ---------------------------------------------------------------------------
// 3. reorder: NO atomics. p = count[row] + rank[e]; single packed 8B store.
// ---------------------------------------------------------------------------
__global__ __launch_bounds__(256)
void reorder_kernel(const int*   __restrict__ rows,
                    const int*   __restrict__ cols,
                    const float* __restrict__ vals, int nE) {
    int e = blockIdx.x * blockDim.x + threadIdx.x;
    if (e >= nE) return;
    int r = __ldg(rows + e);
    int p = __ldg(&g_count[r]) + __ldg(&g_rank[e]);
    g_edge[p] = make_int2(__ldg(cols + e), __float_as_int(__ldg(vals + e)));
}

// ---------------------------------------------------------------------------
// 4. gather: 12 lanes per node, register accumulation, w applied at the end,
//    single output write. No atomics. 4-deep unroll for MLP.
// ---------------------------------------------------------------------------
__global__ __launch_bounds__(256)
void gather_kernel(const float*  __restrict__ x,
                   const float4* __restrict__ w4,
                   float4*       __restrict__ out4) {
    int gid = blockIdx.x * blockDim.x + threadIdx.x;
    int node = gid / CHUNKS;
    int c = gid - node * CHUNKS;
    if (node >= N_NODES) return;

    const int start = __ldg(&g_count[node]);
    const int end   = __ldg(&g_count[node + 1]);

    float4 acc = make_float4(0.f, 0.f, 0.f, 0.f);
    int e = start;
    for (; e + 3 < end; e += 4) {
        int2 m0 = __ldg(g_edge + e + 0);
        int2 m1 = __ldg(g_edge + e + 1);
        int2 m2 = __ldg(g_edge + e + 2);
        int2 m3 = __ldg(g_edge + e + 3);
        float4 a0 = *reinterpret_cast<const float4*>(x + (size_t)m0.x * F_DIM + c * 4);
        float4 a1 = *reinterpret_cast<const float4*>(x + (size_t)m1.x * F_DIM + c * 4);
        float4 a2 = *reinterpret_cast<const float4*>(x + (size_t)m2.x * F_DIM + c * 4);
        float4 a3 = *reinterpret_cast<const float4*>(x + (size_t)m3.x * F_DIM + c * 4);
        float v0 = __int_as_float(m0.y), v1 = __int_as_float(m1.y);
        float v2 = __int_as_float(m2.y), v3 = __int_as_float(m3.y);
        acc.x += v0 * a0.x + v1 * a1.x + v2 * a2.x + v3 * a3.x;
        acc.y += v0 * a0.y + v1 * a1.y + v2 * a2.y + v3 * a3.y;
        acc.z += v0 * a0.z + v1 * a1.z + v2 * a2.z + v3 * a3.z;
        acc.w += v0 * a0.w + v1 * a1.w + v2 * a2.w + v3 * a3.w;
    }
    for (; e < end; e++) {
        int2 m = __ldg(g_edge + e);
        float4 a = *reinterpret_cast<const float4*>(x + (size_t)m.x * F_DIM + c * 4);
        float v = __int_as_float(m.y);
        acc.x += v * a.x;
        acc.y += v * a.y;
        acc.z += v * a.z;
        acc.w += v * a.w;
    }

    float4 wv = __ldg(w4 + c);
    acc.x *= wv.x; acc.y *= wv.y; acc.z *= wv.z; acc.w *= wv.w;

    out4[(size_t)node * CHUNKS + c] = acc;
}

// ---------------------------------------------------------------------------
// Launch
// Inputs: 0 x[1,100000,48] f32 | 1 w[1,48] f32 | 2 rows[1.6M] i32
//         3 cols[1.6M] i32     | 4 vals[1.6M] f32
// Output: f32 [100000, 48]
// ---------------------------------------------------------------------------
extern "C" void kernel_launch(void* const* d_in, const int* in_sizes, int n_in,
                              void* d_out, int out_size) {
    const float* x    = (const float*)d_in[0];
    const float* w    = (const float*)d_in[1];
    const int*   rows = (const int*)  d_in[2];
    const int*   cols = (const int*)  d_in[3];
    const float* vals = (const float*)d_in[4];
    float*       out  = (float*)d_out;

    const int nE = in_sizes[2];

    // 0. zero histogram (capturable async memset; no allocation)
    void* count_ptr = nullptr;
    cudaGetSymbolAddress(&count_ptr, g_count);
    cudaMemsetAsync(count_ptr, 0, (N_NODES + 1) * sizeof(int), 0);

    // 1. histogram + rank
    hist_kernel<<<(nE + 255) / 256, 256>>>(rows, nE);
    // 2. scan
    scan1_kernel<<<SCAN_NBLK, SCAN_TPB>>>();
    scan2_kernel<<<SCAN_NBLK, SCAN_TPB>>>();
    // 3. reorder (atomic-free)
    reorder_kernel<<<(nE + 255) / 256, 256>>>(rows, cols, vals, nE);
    // 4. gather
    {
        int n = N_NODES * CHUNKS;
        gather_kernel<<<(n + 255) / 256, 256>>>(x, (const float4*)w,
                                                (float4*)out);
    }
}